// round 3
// baseline (speedup 1.0000x reference)
#include <cuda_runtime.h>
#include <math_constants.h>

#define BB 4
#define HH 512
#define WW 512
#define HW (HH*WW)
#define NKPT 512
#define CAP 65536
#define NFEAT 128

#define TILE 64
#define HALO 15
#define LDIM (TILE + 2*HALO)     // 94
#define G 3                      // guard ring for unrolled 7-tap loops
#define RROWS (LDIM + 2*G)       // 100
#define SPITCH 104               // padded row stride
#define BUF (RROWS*SPITCH)       // 10400 elems
#define NMS_SMEM (BUF*4*2 + BUF*2)   // s,tmp float + mk,sup uchar = 104000 B
#define NMS_THREADS 512
#define NMS_NW (NMS_THREADS/32)

#define NBINS 512
#define SURVCAP 16384
#define SEL_SMEM (SURVCAP*8)

// Output layout (float32, reference tuple order)
#define OFF_SCORE 0
#define OFF_KPTS  (BB*HW)
#define OFF_FEAS  (OFF_KPTS + BB*NKPT*4)
#define OFF_PIX   (OFF_FEAS + BB*NFEAT*NKPT)

// Scratch
__device__ unsigned long long g_cand[BB*CAP];
__device__ unsigned char g_cmask[BB*HW];
__device__ int g_count[BB];
__device__ int g_sel[BB*NKPT];

__global__ void k_init() {
    if (threadIdx.x < BB) g_count[threadIdx.x] = 0;
}

// Fully fused NMS: gating + init pool + 2 suppression iterations + score2d
// output + candidate compaction. One block per 64x64 output tile.
// All 7-tap loops are fixed-trip (unrolled) over a -inf/0 guard ring.
__global__ __launch_bounds__(NMS_THREADS)
void k_nms(const float* __restrict__ bev,
           const float* __restrict__ raw,
           float* __restrict__ out) {
    extern __shared__ unsigned char smraw[];
    float* sbuf = (float*)smraw;
    float* tbuf = sbuf + BUF;
    unsigned char* mbuf = (unsigned char*)(tbuf + BUF);
    unsigned char* pbuf = mbuf + BUF;
    // interior-origin pointers: coord (ly,lx) in [-G, LDIM+G) is addressable
    float* sc  = sbuf + G*SPITCH + G;
    float* tp  = tbuf + G*SPITCH + G;
    unsigned char* mk  = mbuf + G*SPITCH + G;
    unsigned char* sup = pbuf + G*SPITCH + G;

    const int tid  = threadIdx.x;
    const int wid  = tid >> 5;
    const int lane = tid & 31;
    const int b    = blockIdx.z;
    const int gx0  = blockIdx.x * TILE - HALO;
    const int gy0  = blockIdx.y * TILE - HALO;
    const float* g2 = bev + (b*7 + 2)*HW;
    const float* rw = raw + b*HW;

    // init buffers (guards persist for the whole kernel)
    for (int i = tid; i < BUF; i += NMS_THREADS) {
        sbuf[i] = -CUDART_INF_F;
        tbuf[i] = -CUDART_INF_F;
        mbuf[i] = 0;
        pbuf[i] = 0;
    }
    __syncthreads();

    // load gated scores into interior (out-of-image stays -inf)
    for (int ly = wid; ly < LDIM; ly += NMS_NW) {
        int gy = gy0 + ly;
        if ((unsigned)gy < HH) {
            const float* rwr = rw + gy*WW;
            const float* g2r = g2 + gy*WW;
            for (int lx = lane; lx < LDIM; lx += 32) {
                int gx = gx0 + lx;
                if ((unsigned)gx < WW)
                    sc[ly*SPITCH + lx] = rwr[gx] * (g2r[gx] > 0.f ? 1.f : 0.f);
            }
        }
    }
    __syncthreads();

    // P1: horizontal 7-tap max: sc -> tp
    for (int ly = wid; ly < LDIM; ly += NMS_NW) {
        const float* row = sc + ly*SPITCH;
        for (int lx = lane; lx < LDIM; lx += 32) {
            float m = row[lx-3];
            #pragma unroll
            for (int k = -2; k <= 3; ++k) m = fmaxf(m, row[lx+k]);
            tp[ly*SPITCH + lx] = m;
        }
    }
    __syncthreads();
    // P2: vertical 7-tap max of tp; mk = (max == sc) and in-image (sc >= 0)
    for (int ly = wid; ly < LDIM; ly += NMS_NW) {
        for (int lx = lane; lx < LDIM; lx += 32) {
            const float* col = tp + ly*SPITCH + lx;
            float m = col[-3*SPITCH];
            #pragma unroll
            for (int k = -2; k <= 3; ++k) m = fmaxf(m, col[k*SPITCH]);
            float sv = sc[ly*SPITCH + lx];
            mk[ly*SPITCH + lx] = (m == sv && sv >= 0.f) ? 1 : 0;
        }
    }
    __syncthreads();

    // 2 suppression iterations
    for (int it = 0; it < 2; ++it) {
        // P3: h-dilate mk -> tp (0/1 as float; guards stay -inf)
        for (int ly = wid; ly < LDIM; ly += NMS_NW) {
            const unsigned char* row = mk + ly*SPITCH;
            for (int lx = lane; lx < LDIM; lx += 32) {
                unsigned char m = row[lx-3];
                #pragma unroll
                for (int k = -2; k <= 3; ++k) m |= row[lx+k];
                tp[ly*SPITCH + lx] = m ? 1.f : 0.f;
            }
        }
        __syncthreads();
        // P4: v-dilate tp -> sup
        for (int ly = wid; ly < LDIM; ly += NMS_NW) {
            for (int lx = lane; lx < LDIM; lx += 32) {
                const float* col = tp + ly*SPITCH + lx;
                float m = col[-3*SPITCH];
                #pragma unroll
                for (int k = -2; k <= 3; ++k) m = fmaxf(m, col[k*SPITCH]);
                sup[ly*SPITCH + lx] = (m > 0.f) ? 1 : 0;
            }
        }
        __syncthreads();
        // P5: h-max of supp_scores (sup ? 0 : sc) -> tp
        for (int ly = wid; ly < LDIM; ly += NMS_NW) {
            const float* srow = sc + ly*SPITCH;
            const unsigned char* prow = sup + ly*SPITCH;
            for (int lx = lane; lx < LDIM; lx += 32) {
                float m = -CUDART_INF_F;
                #pragma unroll
                for (int k = -3; k <= 3; ++k) {
                    float v = prow[lx+k] ? 0.f : srow[lx+k];
                    m = fmaxf(m, v);
                }
                tp[ly*SPITCH + lx] = m;
            }
        }
        __syncthreads();
        // P6: v-max of tp; mk |= (max == supp_score) & ~sup & in-image
        for (int ly = wid; ly < LDIM; ly += NMS_NW) {
            for (int lx = lane; lx < LDIM; lx += 32) {
                const float* col = tp + ly*SPITCH + lx;
                float m = col[-3*SPITCH];
                #pragma unroll
                for (int k = -2; k <= 3; ++k) m = fmaxf(m, col[k*SPITCH]);
                int p = ly*SPITCH + lx;
                float sv = sc[p];
                if (!sup[p] && sv >= 0.f && m == sv) mk[p] = 1;
            }
        }
        __syncthreads();
    }

    // emit score2d + candidates (inner 64x64 only)
    for (int ty = wid; ty < TILE; ty += NMS_NW) {
        int gy = blockIdx.y*TILE + ty;
        int ly = ty + HALO;
        for (int tx = lane; tx < TILE; tx += 32) {
            int gx = blockIdx.x*TILE + tx;
            int g = gy*WW + gx;
            int p = ly*SPITCH + (tx + HALO);
            float sv = sc[p];
            out[OFF_SCORE + b*HW + g] = sv;
            unsigned char c = (mk[p] && sv > 0.f) ? 1 : 0;
            g_cmask[b*HW + g] = c;
            if (c) {
                int pos = atomicAdd(&g_count[b], 1);
                if (pos < CAP) {
                    unsigned long long key =
                        ((unsigned long long)__float_as_uint(sv) << 32) |
                        (unsigned int)(HW - 1 - g);
                    g_cand[b*CAP + pos] = key;
                }
            }
        }
    }
}

// One block per batch: histogram -> threshold bin -> compact survivors into
// smem -> exact rank among survivors (== global rank, since any key below the
// threshold bin is strictly smaller than every survivor key).
__global__ __launch_bounds__(1024)
void k_select() {
    extern __shared__ unsigned long long sk[];   // SURVCAP keys
    __shared__ unsigned int h[NBINS];
    __shared__ int scnt;
    __shared__ int thr;

    const int b = blockIdx.x;
    const int tid = threadIdx.x;
    int n = min(g_count[b], CAP);
    const unsigned long long* base = g_cand + (size_t)b*CAP;

    if (tid == 0) { scnt = 0; thr = NBINS; }
    for (int i = tid; i < NBINS; i += blockDim.x) h[i] = 0;
    __syncthreads();

    for (int i = tid; i < n; i += blockDim.x)
        atomicAdd(&h[(unsigned int)(base[i] >> 53)], 1u);
    __syncthreads();

    // suffix sums over bins
    for (int off = 1; off < NBINS; off <<= 1) {
        unsigned int v = 0;
        if (tid < NBINS)
            v = h[tid] + ((tid + off < NBINS) ? h[tid + off] : 0u);
        __syncthreads();
        if (tid < NBINS) h[tid] = v;
        __syncthreads();
    }
    unsigned int target = (unsigned int)min(n, NKPT);
    if (target > 0 && tid < NBINS) {
        bool ge = h[tid] >= target;
        bool nx = (tid + 1 < NBINS) ? (h[tid + 1] >= target) : false;
        if (ge && !nx) thr = tid;
    }
    __syncthreads();

    // compact survivors (bin >= thr) into smem
    int t = thr;
    for (int i = tid; i < n; i += blockDim.x) {
        unsigned long long key = base[i];
        if ((int)(unsigned int)(key >> 53) >= t) {
            int p = atomicAdd(&scnt, 1);
            if (p < SURVCAP) sk[p] = key;
        }
    }
    __syncthreads();

    int m = min(scnt, SURVCAP);
    for (int i = tid; i < m; i += blockDim.x) {
        unsigned long long key = sk[i];
        int r = 0;
        for (int j = 0; j < m; ++j) r += (sk[j] > key) ? 1 : 0;
        if (r < NKPT)
            g_sel[b*NKPT + r] = HW - 1 - (int)(key & 0xffffffffu);
    }
}

// cold fallback: fewer than NKPT candidates -> -1 fillers, ascending index
__global__ void k_fill() {
    int b = blockIdx.x;
    int n = g_count[b];
    if (n >= NKPT) return;
    if (n > CAP) n = CAP;
    int slot = n;
    for (int p = 0; p < HW && slot < NKPT; ++p)
        if (!g_cmask[b*HW + p]) g_sel[b*NKPT + (slot++)] = p;
}

// all gathers in one launch: feats + kpts + pixels
__global__ void k_gather(const float* __restrict__ bev,
                         const float* __restrict__ feat,
                         float* __restrict__ out) {
    int t = blockIdx.x * blockDim.x + threadIdx.x;
    if (t < BB*NKPT) {
        int b = t / NKPT;
        int idx = g_sel[t];
        int u = idx / WW, v = idx - u*WW;
        float4 kv = make_float4(bev[(b*7 + 3)*HW + idx],
                                bev[(b*7 + 4)*HW + idx], 0.f, 1.f);
        ((float4*)(out + OFF_KPTS))[t] = kv;
        float2 pv = make_float2((float)u, (float)v);
        ((float2*)(out + OFF_PIX))[t] = pv;
    }
    if (t >= BB*NFEAT*NKPT) return;
    int k  = t % NKPT;
    int bc = t / NKPT;
    int b  = bc / NFEAT;
    out[OFF_FEAS + t] = feat[bc*HW + g_sel[b*NKPT + k]];
}

extern "C" void kernel_launch(void* const* d_in, const int* in_sizes, int n_in,
                              void* d_out, int out_size) {
    const float* bev  = (const float*)d_in[0];
    const float* raw  = (const float*)d_in[1];
    const float* feat = (const float*)d_in[2];
    float* out = (float*)d_out;

    static bool attr_set = false;
    if (!attr_set) {
        cudaFuncSetAttribute(k_nms, cudaFuncAttributeMaxDynamicSharedMemorySize,
                             NMS_SMEM);
        cudaFuncSetAttribute(k_select,
                             cudaFuncAttributeMaxDynamicSharedMemorySize,
                             SEL_SMEM);
        attr_set = true;
    }

    k_init<<<1, 32>>>();

    dim3 ngrid(WW/TILE, HH/TILE, BB);   // 8 x 8 x 4
    k_nms<<<ngrid, NMS_THREADS, NMS_SMEM>>>(bev, raw, out);

    k_select<<<BB, 1024, SEL_SMEM>>>();
    k_fill<<<BB, 1>>>();

    const int TB = 256;
    k_gather<<<(BB*NFEAT*NKPT + TB - 1)/TB, TB>>>(bev, feat, out);
}

// round 4
// speedup vs baseline: 8.9027x; 8.9027x over previous
#include <cuda_runtime.h>
#include <math_constants.h>

#define BB 4
#define HH 512
#define WW 512
#define HW (HH*WW)
#define NKPT 512
#define CAP 65536
#define NFEAT 128

#define TILE 64
#define HALO 15
#define LDIM (TILE + 2*HALO)     // 94
#define G 3                      // guard ring for unrolled 7-tap loops
#define RROWS (LDIM + 2*G)       // 100
#define SPITCH 100               // row stride (floats / bytes resp.)
#define BUF (RROWS*SPITCH)       // 10000 elems
#define NMS_SMEM (BUF*4*2 + BUF*2)   // 2 float bufs + 2 uchar bufs = 100000 B
#define NMS_THREADS 512
#define NMS_NW (NMS_THREADS/32)

// Output layout (float32, reference tuple order)
#define OFF_SCORE 0
#define OFF_KPTS  (BB*HW)
#define OFF_FEAS  (OFF_KPTS + BB*NKPT*4)
#define OFF_PIX   (OFF_FEAS + BB*NFEAT*NKPT)

// Scratch
__device__ unsigned long long g_cand[BB*CAP];
__device__ unsigned char g_cmask[BB*HW];
__device__ int g_count[BB];
__device__ unsigned long long g_thrkey[BB];
__device__ int g_sel[BB*NKPT];

// ---------------------------------------------------------------------------
// Fused NMS: gating + init pool + 2 suppression iterations + score2d output +
// candidate compaction. One block per 64x64 output tile; 2 blocks/SM.
// All 7-tap loops are fixed-trip (unrolled) over a -inf/0 guard ring.
// ---------------------------------------------------------------------------
__global__ __launch_bounds__(NMS_THREADS, 2)
void k_nms(const float* __restrict__ bev,
           const float* __restrict__ raw,
           float* __restrict__ out) {
    extern __shared__ unsigned char smraw[];
    float* sbuf = (float*)smraw;
    float* tbuf = sbuf + BUF;
    unsigned char* mbuf = (unsigned char*)(tbuf + BUF);
    unsigned char* pbuf = mbuf + BUF;
    // interior-origin pointers: (ly,lx) in [-G, LDIM+G) addressable
    float* sc  = sbuf + G*SPITCH + G;
    float* tp  = tbuf + G*SPITCH + G;
    unsigned char* mk  = mbuf + G*SPITCH + G;
    unsigned char* sup = pbuf + G*SPITCH + G;

    const int tid  = threadIdx.x;
    const int wid  = tid >> 5;
    const int lane = tid & 31;
    const int b    = blockIdx.z;
    const int gx0  = blockIdx.x * TILE - HALO;
    const int gy0  = blockIdx.y * TILE - HALO;
    const float* g2 = bev + (b*7 + 2)*HW;
    const float* rw = raw + b*HW;

    for (int i = tid; i < BUF; i += NMS_THREADS) {
        sbuf[i] = -CUDART_INF_F;
        tbuf[i] = -CUDART_INF_F;
        mbuf[i] = 0;
        pbuf[i] = 0;
    }
    __syncthreads();

    // load gated scores into interior (out-of-image stays -inf)
    for (int ly = wid; ly < LDIM; ly += NMS_NW) {
        int gy = gy0 + ly;
        if ((unsigned)gy < HH) {
            const float* rwr = rw + gy*WW;
            const float* g2r = g2 + gy*WW;
            for (int lx = lane; lx < LDIM; lx += 32) {
                int gx = gx0 + lx;
                if ((unsigned)gx < WW)
                    sc[ly*SPITCH + lx] = rwr[gx] * (g2r[gx] > 0.f ? 1.f : 0.f);
            }
        }
    }
    __syncthreads();

    // P1: horizontal 7-tap max: sc -> tp
    for (int ly = wid; ly < LDIM; ly += NMS_NW) {
        const float* row = sc + ly*SPITCH;
        for (int lx = lane; lx < LDIM; lx += 32) {
            float m = row[lx-3];
            #pragma unroll
            for (int k = -2; k <= 3; ++k) m = fmaxf(m, row[lx+k]);
            tp[ly*SPITCH + lx] = m;
        }
    }
    __syncthreads();
    // P2: vertical 7-tap max of tp; mk = (max == sc) & in-image (sc >= 0)
    for (int ly = wid; ly < LDIM; ly += NMS_NW) {
        for (int lx = lane; lx < LDIM; lx += 32) {
            const float* col = tp + ly*SPITCH + lx;
            float m = col[-3*SPITCH];
            #pragma unroll
            for (int k = -2; k <= 3; ++k) m = fmaxf(m, col[k*SPITCH]);
            float sv = sc[ly*SPITCH + lx];
            mk[ly*SPITCH + lx] = (m == sv && sv >= 0.f) ? 1 : 0;
        }
    }
    __syncthreads();

    for (int it = 0; it < 2; ++it) {
        // P3: h-dilate mk -> tp (0/1 float; guards stay -inf)
        for (int ly = wid; ly < LDIM; ly += NMS_NW) {
            const unsigned char* row = mk + ly*SPITCH;
            for (int lx = lane; lx < LDIM; lx += 32) {
                unsigned char m = row[lx-3];
                #pragma unroll
                for (int k = -2; k <= 3; ++k) m |= row[lx+k];
                tp[ly*SPITCH + lx] = m ? 1.f : 0.f;
            }
        }
        __syncthreads();
        // P4: v-dilate tp -> sup
        for (int ly = wid; ly < LDIM; ly += NMS_NW) {
            for (int lx = lane; lx < LDIM; lx += 32) {
                const float* col = tp + ly*SPITCH + lx;
                float m = col[-3*SPITCH];
                #pragma unroll
                for (int k = -2; k <= 3; ++k) m = fmaxf(m, col[k*SPITCH]);
                sup[ly*SPITCH + lx] = (m > 0.f) ? 1 : 0;
            }
        }
        __syncthreads();
        // P5: h-max of supp_scores (sup ? 0 : sc) -> tp
        for (int ly = wid; ly < LDIM; ly += NMS_NW) {
            const float* srow = sc + ly*SPITCH;
            const unsigned char* prow = sup + ly*SPITCH;
            for (int lx = lane; lx < LDIM; lx += 32) {
                float m = -CUDART_INF_F;
                #pragma unroll
                for (int k = -3; k <= 3; ++k) {
                    float v = prow[lx+k] ? 0.f : srow[lx+k];
                    m = fmaxf(m, v);
                }
                tp[ly*SPITCH + lx] = m;
            }
        }
        __syncthreads();
        // P6: v-max of tp; mk |= (max == supp_score) & ~sup & in-image
        for (int ly = wid; ly < LDIM; ly += NMS_NW) {
            for (int lx = lane; lx < LDIM; lx += 32) {
                const float* col = tp + ly*SPITCH + lx;
                float m = col[-3*SPITCH];
                #pragma unroll
                for (int k = -2; k <= 3; ++k) m = fmaxf(m, col[k*SPITCH]);
                int p = ly*SPITCH + lx;
                float sv = sc[p];
                if (!sup[p] && sv >= 0.f && m == sv) mk[p] = 1;
            }
        }
        __syncthreads();
    }

    // emit score2d + candidates (inner 64x64 only); warp-aggregated atomics
    for (int ty = wid; ty < TILE; ty += NMS_NW) {
        int gy = blockIdx.y*TILE + ty;
        int ly = ty + HALO;
        for (int tx = lane; tx < TILE; tx += 32) {
            int gx = blockIdx.x*TILE + tx;
            int g = gy*WW + gx;
            int p = ly*SPITCH + (tx + HALO);
            float sv = sc[p];
            out[OFF_SCORE + b*HW + g] = sv;
            bool c = (mk[p] && sv > 0.f);
            g_cmask[b*HW + g] = c ? 1 : 0;
            unsigned bal = __ballot_sync(0xffffffffu, c);
            if (bal) {
                int ncand = __popc(bal);
                int base = 0;
                if (lane == __ffs(bal) - 1)
                    base = atomicAdd(&g_count[b], ncand);
                base = __shfl_sync(0xffffffffu, base, __ffs(bal) - 1);
                if (c) {
                    int pos = base + __popc(bal & ((1u << lane) - 1u));
                    if (pos < CAP) {
                        unsigned long long key =
                            ((unsigned long long)__float_as_uint(sv) << 32) |
                            (unsigned int)(HW - 1 - g);
                        g_cand[b*CAP + pos] = key;
                    }
                }
            }
        }
    }
}

// ---------------------------------------------------------------------------
// Two-level 12-bit radix threshold. One block per batch. Produces a 24-bit
// key prefix threshold T such that #{key >= T} >= min(n,512) and the boundary
// bin excess is ~n/4096. Survivor test: key >= g_thrkey[b].
// ---------------------------------------------------------------------------
__global__ __launch_bounds__(1024)
void k_thresh() {
    __shared__ unsigned int hist[4096];
    __shared__ unsigned int csum[1024];
    __shared__ int sBin;
    __shared__ unsigned int sAbove;

    const int b = blockIdx.x;
    const int tid = threadIdx.x;
    const int n = min(g_count[b], CAP);
    const unsigned int target = (unsigned int)min(n, NKPT);
    const unsigned long long* base = g_cand + (size_t)b*CAP;

    if (target == 0) { if (tid == 0) g_thrkey[b] = 0ULL; return; }

    // ---- level 1: bins = key bits [63:52] ----
    for (int i = tid; i < 4096; i += 1024) hist[i] = 0;
    __syncthreads();
    for (int i = tid; i < n; i += 1024)
        atomicAdd(&hist[(unsigned int)(base[i] >> 52)], 1u);
    __syncthreads();
    csum[tid] = hist[4*tid] + hist[4*tid+1] + hist[4*tid+2] + hist[4*tid+3];
    __syncthreads();
    if (tid == 0) {
        unsigned int cum = 0;
        int ch = 0;
        for (int t = 1023; t >= 0; --t) {
            if (cum + csum[t] >= target) { ch = t; break; }
            cum += csum[t];
        }
        int bin = 4*ch;
        for (int bb = 4*ch + 3; bb >= 4*ch; --bb) {
            if (cum + hist[bb] >= target) { bin = bb; break; }
            cum += hist[bb];
        }
        sBin = bin; sAbove = cum;   // cum = count strictly above bin
    }
    __syncthreads();
    const unsigned long long B1 = (unsigned long long)sBin;
    const unsigned int rem = target - sAbove;   // >= 1

    // ---- level 2: bins = key bits [51:40], restricted to level-1 bin ----
    __syncthreads();
    for (int i = tid; i < 4096; i += 1024) hist[i] = 0;
    __syncthreads();
    for (int i = tid; i < n; i += 1024) {
        unsigned long long key = base[i];
        if ((key >> 52) == B1)
            atomicAdd(&hist[(unsigned int)(key >> 40) & 0xFFFu], 1u);
    }
    __syncthreads();
    csum[tid] = hist[4*tid] + hist[4*tid+1] + hist[4*tid+2] + hist[4*tid+3];
    __syncthreads();
    if (tid == 0) {
        unsigned int cum = 0;
        int ch = 0;
        for (int t = 1023; t >= 0; --t) {
            if (cum + csum[t] >= rem) { ch = t; break; }
            cum += csum[t];
        }
        int bin = 4*ch;
        for (int bb = 4*ch + 3; bb >= 4*ch; --bb) {
            if (cum + hist[bb] >= rem) { bin = bb; break; }
            cum += hist[bb];
        }
        g_thrkey[b] = (B1 << 52) | ((unsigned long long)bin << 40);
    }
}

// ---------------------------------------------------------------------------
// Exact rank for survivors (key >= threshold): rank = # keys strictly greater
// over ALL candidates. Key ordering reproduces lax.top_k tie-break exactly.
// One warp per survivor (grid-strided over all candidates).
// ---------------------------------------------------------------------------
__global__ __launch_bounds__(256)
void k_rank() {
    const int b = blockIdx.y;
    const int n = min(g_count[b], CAP);
    if (n == 0) return;
    const unsigned long long T = g_thrkey[b];
    const unsigned long long* base = g_cand + (size_t)b*CAP;
    const int lane = threadIdx.x & 31;
    const int wpb  = blockDim.x >> 5;
    const int nw   = gridDim.x * wpb;

    for (int i = blockIdx.x*wpb + (threadIdx.x >> 5); i < n; i += nw) {
        unsigned long long key = base[i];
        if (key < T) continue;
        int rank = 0;
        int j = lane;
        for (; j + 96 < n; j += 128) {
            unsigned long long a0 = base[j];
            unsigned long long a1 = base[j+32];
            unsigned long long a2 = base[j+64];
            unsigned long long a3 = base[j+96];
            rank += (a0 > key) + (a1 > key) + (a2 > key) + (a3 > key);
        }
        for (; j < n; j += 32) rank += (base[j] > key) ? 1 : 0;
        #pragma unroll
        for (int off = 16; off; off >>= 1)
            rank += __shfl_down_sync(0xffffffffu, rank, off);
        if (lane == 0 && rank < NKPT)
            g_sel[b*NKPT + rank] = HW - 1 - (int)(key & 0xffffffffu);
    }
}

// cold fallback: fewer than NKPT candidates -> -1 fillers, ascending index
__global__ void k_fill() {
    int b = blockIdx.x;
    int n = g_count[b];
    if (n >= NKPT) return;
    if (n > CAP) n = CAP;
    int slot = n;
    for (int p = 0; p < HW && slot < NKPT; ++p)
        if (!g_cmask[b*HW + p]) g_sel[b*NKPT + (slot++)] = p;
}

// all gathers in one launch: feats + kpts + pixels; resets counters for the
// next graph replay (initial state is zero-initialized, so deterministic).
__global__ void k_gather(const float* __restrict__ bev,
                         const float* __restrict__ feat,
                         float* __restrict__ out) {
    int t = blockIdx.x * blockDim.x + threadIdx.x;
    if (blockIdx.x == 0 && threadIdx.x < BB) g_count[threadIdx.x] = 0;
    if (t < BB*NKPT) {
        int b = t / NKPT;
        int idx = g_sel[t];
        int u = idx / WW, v = idx - u*WW;
        float4 kv = make_float4(bev[(b*7 + 3)*HW + idx],
                                bev[(b*7 + 4)*HW + idx], 0.f, 1.f);
        ((float4*)(out + OFF_KPTS))[t] = kv;
        ((float2*)(out + OFF_PIX))[t] = make_float2((float)u, (float)v);
    }
    if (t >= BB*NFEAT*NKPT) return;
    int k  = t % NKPT;
    int bc = t / NKPT;
    int b  = bc / NFEAT;
    out[OFF_FEAS + t] = feat[bc*HW + g_sel[b*NKPT + k]];
}

extern "C" void kernel_launch(void* const* d_in, const int* in_sizes, int n_in,
                              void* d_out, int out_size) {
    const float* bev  = (const float*)d_in[0];
    const float* raw  = (const float*)d_in[1];
    const float* feat = (const float*)d_in[2];
    float* out = (float*)d_out;

    static bool attr_set = false;
    if (!attr_set) {
        cudaFuncSetAttribute(k_nms, cudaFuncAttributeMaxDynamicSharedMemorySize,
                             NMS_SMEM);
        attr_set = true;
    }

    dim3 ngrid(WW/TILE, HH/TILE, BB);   // 8 x 8 x 4
    k_nms<<<ngrid, NMS_THREADS, NMS_SMEM>>>(bev, raw, out);

    k_thresh<<<BB, 1024>>>();

    dim3 rgrid(64, BB);                 // 512 warps per batch
    k_rank<<<rgrid, 256>>>();

    k_fill<<<BB, 1>>>();

    const int TB = 256;
    k_gather<<<(BB*NFEAT*NKPT + TB - 1)/TB, TB>>>(bev, feat, out);
}

// round 6
// speedup vs baseline: 13.6141x; 1.5292x over previous
#include <cuda_runtime.h>
#include <math_constants.h>

#define BB 4
#define HH 512
#define WW 512
#define HW (HH*WW)
#define NKPT 512
#define CAP 65536
#define NFEAT 128

#define TILE 64
#define HALO 15
#define LDIM (TILE + 2*HALO)     // 94
#define G 3                      // guard ring
#define RROWS (LDIM + 2*G)       // 100
#define SPITCH 100
#define BUF (RROWS*SPITCH)       // 10000
#define WPR 5                    // bit-words per row (slots 0,4 = zero guards)
#define NMS_SMEM (BUF*4*2 + RROWS*WPR*4*3)   // 86000 B
#define NMS_THREADS 512
#define NMS_NW (NMS_THREADS/32)

#define SURVCAP 4096

// Output layout (float32, reference tuple order)
#define OFF_SCORE 0
#define OFF_KPTS  (BB*HW)
#define OFF_FEAS  (OFF_KPTS + BB*NKPT*4)
#define OFF_PIX   (OFF_FEAS + BB*NFEAT*NKPT)

// Scratch
__device__ unsigned long long g_cand[BB*CAP];
__device__ unsigned char g_cmask[BB*HW];
__device__ int g_count[BB];
__device__ unsigned long long g_thrkey[BB];
__device__ int g_sel[BB*NKPT];

// ---------------------------------------------------------------------------
// Fused NMS. One block per 64x64 tile. Float pools in smem; mask/dilation as
// bitboards (ballot-written words, funnel-shift h-dilate, word-OR v-dilate).
// Emit (score2d + candidates) fused into the final pass.
// ---------------------------------------------------------------------------
__global__ __launch_bounds__(NMS_THREADS, 2)
void k_nms(const float* __restrict__ bev,
           const float* __restrict__ raw,
           float* __restrict__ out) {
    extern __shared__ unsigned char smraw[];
    float* sbuf = (float*)smraw;
    float* tbuf = sbuf + BUF;
    unsigned int* mkw = (unsigned int*)(tbuf + BUF);  // max_mask bits
    unsigned int* hbw = mkw + RROWS*WPR;              // h-dilated bits
    unsigned int* spw = hbw + RROWS*WPR;              // supp (7x7 dil) bits
    float* sc = sbuf + G*SPITCH + G;
    float* tp = tbuf + G*SPITCH + G;

    const int tid  = threadIdx.x;
    const int wid  = tid >> 5;
    const int lane = tid & 31;
    const int b    = blockIdx.z;
    const int gx0  = blockIdx.x * TILE - HALO;
    const int gy0  = blockIdx.y * TILE - HALO;
    const float* g2 = bev + (b*7 + 2)*HW;
    const float* rw = raw + b*HW;

    for (int i = tid; i < BUF; i += NMS_THREADS) {
        sbuf[i] = -CUDART_INF_F;
        tbuf[i] = -CUDART_INF_F;
    }
    for (int i = tid; i < RROWS*WPR; i += NMS_THREADS) {
        mkw[i] = 0; hbw[i] = 0; spw[i] = 0;
    }
    __syncthreads();

    // load gated scores (out-of-image stays -inf)
    for (int ly = wid; ly < LDIM; ly += NMS_NW) {
        int gy = gy0 + ly;
        if ((unsigned)gy < HH) {
            const float* rwr = rw + gy*WW;
            const float* g2r = g2 + gy*WW;
            for (int lx = lane; lx < LDIM; lx += 32) {
                int gx = gx0 + lx;
                if ((unsigned)gx < WW)
                    sc[ly*SPITCH + lx] = rwr[gx] * (g2r[gx] > 0.f ? 1.f : 0.f);
            }
        }
    }
    __syncthreads();

    // P1: h 7-max sc -> tp
    for (int ly = wid; ly < LDIM; ly += NMS_NW) {
        const float* row = sc + ly*SPITCH;
        for (int lx = lane; lx < LDIM; lx += 32) {
            float m = row[lx-3];
            #pragma unroll
            for (int k = -2; k <= 3; ++k) m = fmaxf(m, row[lx+k]);
            tp[ly*SPITCH + lx] = m;
        }
    }
    __syncthreads();
    // P2: v 7-max of tp; mk bit = (max == sc) & in-image; ballot word write
    for (int ly = wid; ly < LDIM; ly += NMS_NW) {
        for (int g = 0; g < 3; ++g) {
            int lx = g*32 + lane;
            bool pred = false;
            if (lx < LDIM) {
                const float* col = tp + ly*SPITCH + lx;
                float m = col[-3*SPITCH];
                #pragma unroll
                for (int k = -2; k <= 3; ++k) m = fmaxf(m, col[k*SPITCH]);
                float sv = sc[ly*SPITCH + lx];
                pred = (m == sv && sv >= 0.f);
            }
            unsigned bal = __ballot_sync(0xffffffffu, pred);
            if (lane == 0) mkw[(ly+G)*WPR + 1 + g] = bal;
        }
    }
    __syncthreads();

    for (int it = 0; it < 2; ++it) {
        // P3: h-dilate mk bits (funnel shifts), 300 word tasks
        for (int t = tid; t < 300; t += NMS_THREADS) {
            int row = t / 3, w = t % 3 + 1;
            const unsigned int* mr = mkw + row*WPR;
            unsigned a = mr[w-1], c = mr[w], d = mr[w+1];
            unsigned res = c;
            res |= __funnelshift_l(a, c, 1) | __funnelshift_r(c, d, 1);
            res |= __funnelshift_l(a, c, 2) | __funnelshift_r(c, d, 2);
            res |= __funnelshift_l(a, c, 3) | __funnelshift_r(c, d, 3);
            hbw[row*WPR + w] = res;
        }
        __syncthreads();
        // P4: v-dilate (word OR of 7 rows), rows 3..96
        for (int t = tid; t < 282; t += NMS_THREADS) {
            int row = t / 3 + 3, w = t % 3 + 1;
            unsigned r = 0;
            #pragma unroll
            for (int k = -3; k <= 3; ++k) r |= hbw[(row+k)*WPR + w];
            spw[row*WPR + w] = r;
        }
        __syncthreads();
        // P5: h 7-max of (supbit ? 0 : sc) -> tp
        for (int ly = wid; ly < LDIM; ly += NMS_NW) {
            const float* srow = sc + ly*SPITCH;
            const unsigned int* sr = spw + (ly+G)*WPR + 1;
            for (int lx = lane; lx < LDIM; lx += 32) {
                float m = -CUDART_INF_F;
                #pragma unroll
                for (int k = -3; k <= 3; ++k) {
                    int B = lx + k;
                    unsigned wv = sr[B >> 5];
                    float v = ((wv >> (B & 31)) & 1u) ? 0.f : srow[lx+k];
                    m = fmaxf(m, v);
                }
                tp[ly*SPITCH + lx] = m;
            }
        }
        __syncthreads();
        // P6: v 7-max of tp; cond = (!sup & sv>=0 & m==sv)
        //     it=0: mk |= cond.  it=1: fused emit with final mask.
        for (int ly = wid; ly < LDIM; ly += NMS_NW) {
            const unsigned int* sr = spw + (ly+G)*WPR + 1;
            unsigned int* mr = mkw + (ly+G)*WPR + 1;
            for (int g = 0; g < 3; ++g) {
                int lx = g*32 + lane;
                bool cond = false;
                float sv = 0.f;
                unsigned oldw = mr[g];
                if (lx < LDIM) {
                    const float* col = tp + ly*SPITCH + lx;
                    float m = col[-3*SPITCH];
                    #pragma unroll
                    for (int k = -2; k <= 3; ++k) m = fmaxf(m, col[k*SPITCH]);
                    sv = sc[ly*SPITCH + lx];
                    unsigned supb = (sr[g] >> lane) & 1u;
                    cond = (!supb && sv >= 0.f && m == sv);
                }
                if (it == 0) {
                    unsigned bal = __ballot_sync(0xffffffffu, cond);
                    if (lane == 0 && bal) mr[g] |= bal;
                } else {
                    bool c = false;
                    int gg = 0;
                    int ty = ly - HALO, tx = lx - HALO;
                    bool inter = ((unsigned)ty < TILE) && ((unsigned)tx < TILE)
                                 && (lx < LDIM);
                    if (inter) {
                        bool fm = cond || (((oldw >> lane) & 1u) != 0u);
                        int gy = blockIdx.y*TILE + ty;
                        int gx = blockIdx.x*TILE + tx;
                        gg = gy*WW + gx;
                        out[OFF_SCORE + b*HW + gg] = sv;
                        c = fm && (sv > 0.f);
                        g_cmask[b*HW + gg] = c ? 1 : 0;
                    }
                    unsigned cb = __ballot_sync(0xffffffffu, c);
                    if (cb) {
                        int ldr = __ffs(cb) - 1;
                        int basep = 0;
                        if (lane == ldr)
                            basep = atomicAdd(&g_count[b], __popc(cb));
                        basep = __shfl_sync(0xffffffffu, basep, ldr);
                        if (c) {
                            int pos = basep + __popc(cb & ((1u << lane) - 1u));
                            if (pos < CAP) {
                                unsigned long long key =
                                    ((unsigned long long)__float_as_uint(sv) << 32)
                                    | (unsigned int)(HW - 1 - gg);
                                g_cand[b*CAP + pos] = key;
                            }
                        }
                    }
                }
            }
        }
        __syncthreads();
    }
}

// ---------------------------------------------------------------------------
// Warp-aggregated histogram add. CONVERGENCE-SAFE: vm is computed by all 32
// lanes; then exactly the lanes in vm call __match_any_sync with mask vm.
// ---------------------------------------------------------------------------
__device__ __forceinline__ void hist_add(unsigned int* h, unsigned bin,
                                         bool valid) {
    unsigned vm = __ballot_sync(0xffffffffu, valid);
    if (valid) {
        unsigned peers = __match_any_sync(vm, bin);
        int lane = threadIdx.x & 31;
        if (lane == __ffs(peers) - 1)
            atomicAdd(&h[bin], (unsigned)__popc(peers));
    }
}

// ---------------------------------------------------------------------------
// Two-level 12-bit radix threshold, parallel suffix-scan boundary search.
// T has zero low 40 bits => every non-survivor key < every survivor key.
// ---------------------------------------------------------------------------
__global__ __launch_bounds__(1024)
void k_thresh() {
    __shared__ unsigned int h[4096];
    __shared__ unsigned int cs[1025];
    __shared__ int sBin;
    __shared__ unsigned int sAbove;

    const int b = blockIdx.x;
    const int tid = threadIdx.x;
    const int n = min(g_count[b], CAP);
    const unsigned int target = (unsigned int)min(n, NKPT);
    const unsigned long long* base = g_cand + (size_t)b*CAP;

    if (target == 0) { if (tid == 0) g_thrkey[b] = 0ULL; return; }
    const int nR = (n + 1023) & ~1023;

    // ---- level 1: bins = key bits [63:52] ----
    for (int i = tid; i < 4096; i += 1024) h[i] = 0;
    if (tid == 0) cs[1024] = 0;
    __syncthreads();
    for (int i = tid; i < nR; i += 1024) {
        bool valid = i < n;
        unsigned bin = valid ? (unsigned)(base[i] >> 52) : 0u;
        hist_add(h, bin, valid);
    }
    __syncthreads();
    unsigned h0 = h[4*tid], h1 = h[4*tid+1], h2 = h[4*tid+2], h3 = h[4*tid+3];
    cs[tid] = h0 + h1 + h2 + h3;
    __syncthreads();
    for (int off = 1; off < 1024; off <<= 1) {
        unsigned v = cs[tid] + ((tid + off < 1024) ? cs[tid + off] : 0u);
        __syncthreads();
        cs[tid] = v;
        __syncthreads();
    }
    {
        unsigned s4 = cs[tid + 1];
        unsigned s3 = h3 + s4, s2 = h2 + s3, s1 = h1 + s2, s0 = h0 + s1;
        unsigned sf[5] = {s0, s1, s2, s3, s4};
        #pragma unroll
        for (int i = 0; i < 4; ++i)
            if (sf[i] >= target && sf[i+1] < target) {
                sBin = 4*tid + i; sAbove = sf[i+1];
            }
    }
    __syncthreads();
    const unsigned long long B1 = (unsigned long long)sBin;
    const unsigned int rem = target - sAbove;   // >= 1

    // ---- level 2: bins = key bits [51:40], restricted to level-1 bin ----
    __syncthreads();
    for (int i = tid; i < 4096; i += 1024) h[i] = 0;
    __syncthreads();
    for (int i = tid; i < nR; i += 1024) {
        bool valid = false;
        unsigned bin = 0;
        if (i < n) {
            unsigned long long key = base[i];
            if ((key >> 52) == B1) {
                valid = true;
                bin = (unsigned)(key >> 40) & 0xFFFu;
            }
        }
        hist_add(h, bin, valid);
    }
    __syncthreads();
    h0 = h[4*tid]; h1 = h[4*tid+1]; h2 = h[4*tid+2]; h3 = h[4*tid+3];
    cs[tid] = h0 + h1 + h2 + h3;
    __syncthreads();
    for (int off = 1; off < 1024; off <<= 1) {
        unsigned v = cs[tid] + ((tid + off < 1024) ? cs[tid + off] : 0u);
        __syncthreads();
        cs[tid] = v;
        __syncthreads();
    }
    {
        unsigned s4 = cs[tid + 1];
        unsigned s3 = h3 + s4, s2 = h2 + s3, s1 = h1 + s2, s0 = h0 + s1;
        unsigned sf[5] = {s0, s1, s2, s3, s4};
        #pragma unroll
        for (int i = 0; i < 4; ++i)
            if (sf[i] >= rem && sf[i+1] < rem)
                g_thrkey[b] = (B1 << 52) |
                              ((unsigned long long)(4*tid + i) << 40);
    }
}

// ---------------------------------------------------------------------------
// Compact survivors (key >= T) to smem; rank among survivors == global rank.
// O(m^2) broadcast smem compares, m ~ 512 + ties. Cold fallbacks included.
// ---------------------------------------------------------------------------
__global__ __launch_bounds__(1024)
void k_select() {
    __shared__ unsigned long long sk[SURVCAP];
    __shared__ int scnt;
    const int b = blockIdx.x;
    const int tid = threadIdx.x;
    const int n = min(g_count[b], CAP);
    if (tid == 0) scnt = 0;
    __syncthreads();
    const unsigned long long T = g_thrkey[b];
    const unsigned long long* base = g_cand + (size_t)b*CAP;

    for (int i = tid; i < n; i += 1024) {
        unsigned long long key = base[i];
        if (key >= T) {
            int p = atomicAdd(&scnt, 1);
            if (p < SURVCAP) sk[p] = key;
        }
    }
    __syncthreads();
    int m = scnt;

    if (m <= SURVCAP) {
        for (int i = tid; i < m; i += 1024) {
            unsigned long long key = sk[i];
            int r = 0;
            for (int j = 0; j < m; ++j) r += (sk[j] > key) ? 1 : 0;
            if (r < NKPT)
                g_sel[b*NKPT + r] = HW - 1 - (int)(key & 0xffffffffu);
        }
    } else {
        // cold: exact rank via global scans, warp per survivor
        int lane = tid & 31, w = tid >> 5;
        for (int i = w; i < n; i += 32) {
            unsigned long long key = base[i];
            if (key < T) continue;
            int r = 0;
            for (int j = lane; j < n; j += 32) r += (base[j] > key) ? 1 : 0;
            #pragma unroll
            for (int off = 16; off; off >>= 1)
                r += __shfl_down_sync(0xffffffffu, r, off);
            if (lane == 0 && r < NKPT)
                g_sel[b*NKPT + r] = HW - 1 - (int)(key & 0xffffffffu);
        }
    }

    // cold: fewer than NKPT candidates -> ascending non-candidate indices
    if (n < NKPT) {
        __syncthreads();
        if (tid == 0) {
            int slot = n;
            for (int p = 0; p < HW && slot < NKPT; ++p)
                if (!g_cmask[b*HW + p]) g_sel[b*NKPT + (slot++)] = p;
        }
    }
}

// all gathers + counter reset for next graph replay
__global__ void k_gather(const float* __restrict__ bev,
                         const float* __restrict__ feat,
                         float* __restrict__ out) {
    int t = blockIdx.x * blockDim.x + threadIdx.x;
    if (blockIdx.x == 0 && threadIdx.x < BB) g_count[threadIdx.x] = 0;
    if (t < BB*NKPT) {
        int b = t / NKPT;
        int idx = g_sel[t];
        int u = idx / WW, v = idx - u*WW;
        float4 kv = make_float4(bev[(b*7 + 3)*HW + idx],
                                bev[(b*7 + 4)*HW + idx], 0.f, 1.f);
        ((float4*)(out + OFF_KPTS))[t] = kv;
        ((float2*)(out + OFF_PIX))[t] = make_float2((float)u, (float)v);
    }
    if (t >= BB*NFEAT*NKPT) return;
    int k  = t % NKPT;
    int bc = t / NKPT;
    int b  = bc / NFEAT;
    out[OFF_FEAS + t] = feat[bc*HW + g_sel[b*NKPT + k]];
}

extern "C" void kernel_launch(void* const* d_in, const int* in_sizes, int n_in,
                              void* d_out, int out_size) {
    const float* bev  = (const float*)d_in[0];
    const float* raw  = (const float*)d_in[1];
    const float* feat = (const float*)d_in[2];
    float* out = (float*)d_out;

    static bool attr_set = false;
    if (!attr_set) {
        cudaFuncSetAttribute(k_nms, cudaFuncAttributeMaxDynamicSharedMemorySize,
                             NMS_SMEM);
        attr_set = true;
    }

    dim3 ngrid(WW/TILE, HH/TILE, BB);   // 8 x 8 x 4
    k_nms<<<ngrid, NMS_THREADS, NMS_SMEM>>>(bev, raw, out);
    k_thresh<<<BB, 1024>>>();
    k_select<<<BB, 1024>>>();
    const int TB = 256;
    k_gather<<<(BB*NFEAT*NKPT + TB - 1)/TB, TB>>>(bev, feat, out);
}